// round 13
// baseline (speedup 1.0000x reference)
#include <cuda_runtime.h>
#include <cuda_fp16.h>
#include <cstdint>

#define Bn 2
#define Dn 1024
#define Tn 2048
#define Hn 16
#define DHn 64
#define NBH (Bn*Hn)

// --------------- global scratch (plain fp16 everywhere) ---------------
__device__ __align__(16) __half gx [(size_t)Bn*Dn*Tn];          // x fp16
__device__ __align__(16) __half gw [(size_t)3*Hn*Dn*DHn];       // w fp16
__device__ __align__(16) __half g_q[(size_t)NBH*Tn*DHn];        // q [bh][t][dh], pre-scaled
__device__ __align__(16) __half g_k[(size_t)NBH*Tn*DHn];        // k [bh][t][dh]
__device__ __align__(16) __half g_v[(size_t)NBH*DHn*Tn];        // v [bh][dh][t]

// --------------- helpers ---------------
static __device__ __forceinline__ uint32_t smem_u32(const void* p){
    uint32_t a;
    asm("{ .reg .u64 t; cvta.to.shared.u64 t, %1; cvt.u32.u64 %0, t; }" : "=r"(a) : "l"(p));
    return a;
}
static __device__ __forceinline__ void cpa16(uint32_t dst, const void* src){
    asm volatile("cp.async.cg.shared.global [%0], [%1], 16;" :: "r"(dst), "l"(src));
}
#define CP_COMMIT() asm volatile("cp.async.commit_group;" ::: "memory")
#define CP_WAIT1()  asm volatile("cp.async.wait_group 1;" ::: "memory")

static __device__ __forceinline__ void ldsm4(uint32_t* r, uint32_t a){
    asm volatile("ldmatrix.sync.aligned.m8n8.x4.shared.b16 {%0,%1,%2,%3}, [%4];"
        : "=r"(r[0]),"=r"(r[1]),"=r"(r[2]),"=r"(r[3]) : "r"(a));
}
static __device__ __forceinline__ void ldsm4t(uint32_t* r, uint32_t a){
    asm volatile("ldmatrix.sync.aligned.m8n8.x4.trans.shared.b16 {%0,%1,%2,%3}, [%4];"
        : "=r"(r[0]),"=r"(r[1]),"=r"(r[2]),"=r"(r[3]) : "r"(a));
}
static __device__ __forceinline__ void mma16816(float* c, const uint32_t* a, const uint32_t* b){
    asm volatile("mma.sync.aligned.m16n8k16.row.col.f32.f16.f16.f32 "
        "{%0,%1,%2,%3}, {%4,%5,%6,%7}, {%8,%9}, {%0,%1,%2,%3};"
        : "+f"(c[0]), "+f"(c[1]), "+f"(c[2]), "+f"(c[3])
        : "r"(a[0]), "r"(a[1]), "r"(a[2]), "r"(a[3]), "r"(b[0]), "r"(b[1]));
}
static __device__ __forceinline__ uint32_t packh2(float e0, float e1){
    __half2 hv = __floats2half2_rn(e0, e1);
    return *(uint32_t*)&hv;
}
static __device__ __forceinline__ uint32_t ex2h2(uint32_t x){
    uint32_t r;
    asm("ex2.approx.f16x2 %0, %1;" : "=r"(r) : "r"(x));
    return r;
}

// --------------- prepass: fp32 -> fp16 (single fused kernel) ---------------
__global__ __launch_bounds__(256) void conv_kernel(const float4* __restrict__ xs, int nx4,
                                                   const float4* __restrict__ ws, int nw4){
    uint2* dx = (uint2*)gx;
    uint2* dw = (uint2*)gw;
    const int total = nx4 + nw4;
    for (int i = blockIdx.x*blockDim.x + threadIdx.x; i < total; i += gridDim.x*blockDim.x){
        float4 v = (i < nx4) ? xs[i] : ws[i - nx4];
        uint2 u;
        u.x = packh2(v.x, v.y);
        u.y = packh2(v.z, v.w);
        if (i < nx4) dx[i] = u; else dw[i - nx4] = u;
    }
}

// =====================================================================
// QKV GEMM: C[t,dh] = sum_d x[b,d,t] * w[nh,d,dh]; CTA tile 256t x 64dh,
// 4 warps, warp = 64t x 64dh -> ldsm:MMA = 1:4 per op (8 ldsm / 32 MMA
// per k16). grid=(16,48), block 128, 2 CTAs/SM.
// stage: A 32K ([d][t], 512B rows, swizzle g^(d&7)) | B 8K = 40K, x2.
// q stored pre-scaled by 0.125*log2e; v transposed to [dh][t].
// =====================================================================
#define QSTG 40960

__global__ __launch_bounds__(128, 2) void qkv_mma_kernel(){
    extern __shared__ char sm[];
    const uint32_t sb = smem_u32(sm);
    const int tid = threadIdx.x, lane = tid & 31, wid = tid >> 5;   // wid 0..3
    const int t0 = (blockIdx.x & 7) * 256;
    const int b  = blockIdx.x >> 3;
    const int nh = blockIdx.y;

    const __half* xp = gx + (size_t)b * Dn * Tn + t0;
    const __half* wp = gw + (size_t)nh * Dn * DHn;

    auto issue = [&](int s){
        const int d0 = s * 64;
        const uint32_t bi = sb + (s & 1) * QSTG;
        #pragma unroll
        for (int i = 0; i < 16; i++){          // A: 2048 16B-chunks (64d x 32g)
            int c = tid + i * 128;
            int d = c >> 5, g = c & 31;
            cpa16(bi + d * 512 + ((g ^ (d & 7)) << 4),
                  xp + (size_t)(d0 + d) * Tn + g * 8);
        }
        #pragma unroll
        for (int i = 0; i < 4; i++){           // B: 512 chunks (64d x 8g)
            int c = tid + i * 128;
            int d = c >> 3, g = c & 7;
            cpa16(bi + 32768 + d * 128 + ((g ^ (d & 7)) << 4),
                  wp + (size_t)(d0 + d) * DHn + g * 8);
        }
    };

    float acc[4][8][4];
    #pragma unroll
    for (int i = 0; i < 4; i++)
        #pragma unroll
        for (int j = 0; j < 8; j++)
            #pragma unroll
            for (int k = 0; k < 4; k++) acc[i][j][k] = 0.f;

    issue(0); CP_COMMIT();
    issue(1); CP_COMMIT();

    #pragma unroll 1
    for (int s = 0; s < 16; s++){
        CP_WAIT1();
        __syncthreads();
        const uint32_t base = sb + (s & 1) * QSTG;

        #pragma unroll
        for (int k16 = 0; k16 < 4; k16++){
            const int k0 = k16 * 16;
            uint32_t ah[4][4];
            {
                int k = k0 + (lane & 7) + ((lane & 16) ? 8 : 0);
                #pragma unroll
                for (int mt = 0; mt < 4; mt++){
                    int gm = ((wid * 64 + mt * 16) >> 3) + ((lane & 8) ? 1 : 0);
                    ldsm4t(ah[mt], base + k * 512 + ((gm ^ (k & 7)) << 4));
                }
            }
            {
                int k = k0 + (lane & 7) + ((lane & 8) ? 8 : 0);
                #pragma unroll
                for (int p = 0; p < 4; p++){
                    int gn = p * 2 + ((lane & 16) ? 1 : 0);
                    uint32_t bw[4];
                    ldsm4t(bw, base + 32768 + k * 128 + ((gn ^ (k & 7)) << 4));
                    #pragma unroll
                    for (int q = 0; q < 2; q++)
                        #pragma unroll
                        for (int mt = 0; mt < 4; mt++)
                            mma16816(acc[mt][p * 2 + q], ah[mt], &bw[q*2]);
                }
            }
        }
        __syncthreads();
        if (s + 2 < 16) issue(s + 2);
        CP_COMMIT();
    }
    __syncthreads();

    // epilogue
    const int n = nh >> 4, h = nh & 15, bh = b * Hn + h;
    const int r = lane >> 2, c2 = (lane & 3) * 2;
    if (n < 2){
        __half* dst = (n == 0 ? g_q : g_k) + (size_t)bh * Tn * DHn;
        const float sc = (n == 0) ? 0.125f * 1.44269504088896f : 1.0f;
        #pragma unroll
        for (int mt = 0; mt < 4; mt++)
            #pragma unroll
            for (int nt = 0; nt < 8; nt++){
                int t = t0 + wid * 64 + mt * 16 + r;
                int col = nt * 8 + c2;
                *(uint32_t*)(dst + (size_t)t * DHn + col) =
                    packh2(acc[mt][nt][0] * sc, acc[mt][nt][1] * sc);
                *(uint32_t*)(dst + (size_t)(t + 8) * DHn + col) =
                    packh2(acc[mt][nt][2] * sc, acc[mt][nt][3] * sc);
            }
    } else {
        float* Cs = (float*)sm;   // [64 dh][256 t]
        #pragma unroll
        for (int mt = 0; mt < 4; mt++)
            #pragma unroll
            for (int nt = 0; nt < 8; nt++){
                int t = wid * 64 + mt * 16 + r;
                int col = nt * 8 + c2;
                Cs[col * 256 + t]           = acc[mt][nt][0];
                Cs[(col + 1) * 256 + t]     = acc[mt][nt][1];
                Cs[col * 256 + t + 8]       = acc[mt][nt][2];
                Cs[(col + 1) * 256 + t + 8] = acc[mt][nt][3];
            }
        __syncthreads();
        const int dh = tid >> 1, q0 = (tid & 1) * 128;
        __half* ov = g_v + ((size_t)bh * DHn + dh) * Tn + t0 + q0;
        #pragma unroll
        for (int i = 0; i < 128; i += 2)
            *(uint32_t*)(ov + i) = packh2(Cs[dh * 256 + q0 + i], Cs[dh * 256 + q0 + i + 1]);
    }
}

// =====================================================================
// Attention: 128 q-rows per block, 4 warps (32 q-rows each), plain fp16.
// Key tile processed in TWO 32-key halves to halve live S registers ->
// fits 3 CTAs/SM (regs <= 170, smem 48K). Row sums via ones-MMA.
// =====================================================================
#define AQR 16384
#define AKVS 16384

__global__ __launch_bounds__(128, 3) void attn_mma_kernel(float* __restrict__ out){
    extern __shared__ char sm[];
    const uint32_t sb = smem_u32(sm);
    const int tid = threadIdx.x, lane = tid & 31, wid = tid >> 5;   // wid 0..3
    const int t0 = blockIdx.x * 128;
    const int bh = blockIdx.y;
    const int b = bh >> 4, h = bh & 15;

    const __half* kb = g_k + (size_t)bh * Tn * DHn;
    const __half* vb = g_v + (size_t)bh * DHn * Tn;

    auto issue_kv = [&](int kt){
        const int tk = kt * 64;
        const uint32_t bi = sb + AQR + (kt & 1) * AKVS;
        #pragma unroll
        for (int i = 0; i < 4; i++){
            int c = tid + i * 128;
            int row = c >> 3, g = c & 7;
            cpa16(bi + row * 128 + ((g ^ (row & 7)) << 4),
                  kb + (size_t)(tk + row) * DHn + g * 8);
            cpa16(bi + 8192 + row * 128 + ((g ^ (row & 7)) << 4),
                  vb + (size_t)row * Tn + tk + g * 8);
        }
    };

    {
        const __half* qb = g_q + ((size_t)bh * Tn + t0) * DHn;
        #pragma unroll
        for (int i = 0; i < 8; i++){
            int c = tid + i * 128;
            int row = c >> 3, g = c & 7;
            cpa16(sb + row * 128 + ((g ^ (row & 7)) << 4),
                  qb + (size_t)row * DHn + g * 8);
        }
        issue_kv(0); CP_COMMIT();
        issue_kv(1); CP_COMMIT();
    }
    CP_WAIT1();
    __syncthreads();

    // Q fragments: warp owns rows wid*32 .. wid*32+31 (two m16 frags)
    uint32_t qf[2][4][4];
    #pragma unroll
    for (int mt = 0; mt < 2; mt++){
        const int m = wid * 32 + mt * 16 + (lane & 15);
        #pragma unroll
        for (int k16 = 0; k16 < 4; k16++){
            int g = k16 * 2 + ((lane & 16) ? 1 : 0);
            ldsm4(qf[mt][k16], sb + m * 128 + ((g ^ (m & 7)) << 4));
        }
    }

    float o[2][8][4];
    #pragma unroll
    for (int mt = 0; mt < 2; mt++)
        #pragma unroll
        for (int i = 0; i < 8; i++)
            #pragma unroll
            for (int j = 0; j < 4; j++) o[mt][i][j] = 0.f;
    float ol[2][4];   // row-sum accumulator via ones-MMA
    #pragma unroll
    for (int mt = 0; mt < 2; mt++)
        #pragma unroll
        for (int j = 0; j < 4; j++) ol[mt][j] = 0.f;
    const uint32_t ones2 = 0x3C003C00u;          // fp16 {1,1}
    const uint32_t bone[2] = {ones2, ones2};

    #pragma unroll 1
    for (int kt = 0; kt < Tn / 64; kt++){
        if (kt > 0){ CP_WAIT1(); __syncthreads(); }
        const uint32_t bi = sb + AQR + (kt & 1) * AKVS;
        const int nn = (lane & 7) + ((lane & 16) ? 8 : 0);

        #pragma unroll
        for (int half = 0; half < 2; half++){
            // ---- S (log2 domain) for 32 keys ----
            float s[2][4][4];
            #pragma unroll
            for (int mt = 0; mt < 2; mt++)
                #pragma unroll
                for (int i = 0; i < 4; i++)
                    #pragma unroll
                    for (int j = 0; j < 4; j++) s[mt][i][j] = 0.f;

            #pragma unroll
            for (int k16 = 0; k16 < 4; k16++){
                const int gsel = k16 * 2 + ((lane & 8) ? 1 : 0);
                #pragma unroll
                for (int p = 0; p < 2; p++){
                    int nrow = half * 32 + p * 16 + nn;
                    uint32_t bk[4];
                    ldsm4(bk, bi + nrow * 128 + ((gsel ^ (nrow & 7)) << 4));
                    #pragma unroll
                    for (int q = 0; q < 2; q++)
                        #pragma unroll
                        for (int mt = 0; mt < 2; mt++)
                            mma16816(s[mt][p * 2 + q], qf[mt][k16], &bk[q*2]);
                }
            }

            // ---- P = exp2(S) fp16x2; rowsum + PV MMAs ----
            #pragma unroll
            for (int j = 0; j < 2; j++){
                uint32_t pa[2][4];
                #pragma unroll
                for (int mt = 0; mt < 2; mt++){
                    pa[mt][0] = ex2h2(packh2(s[mt][2*j][0],   s[mt][2*j][1]));
                    pa[mt][1] = ex2h2(packh2(s[mt][2*j][2],   s[mt][2*j][3]));
                    pa[mt][2] = ex2h2(packh2(s[mt][2*j+1][0], s[mt][2*j+1][1]));
                    pa[mt][3] = ex2h2(packh2(s[mt][2*j+1][2], s[mt][2*j+1][3]));
                    mma16816(ol[mt], pa[mt], bone);   // row sums
                }
                const int gsel = (half * 2 + j) * 2 + ((lane & 8) ? 1 : 0);
                #pragma unroll
                for (int p = 0; p < 4; p++){
                    int nrow = p * 16 + nn;
                    uint32_t bv[4];
                    ldsm4(bv, bi + 8192 + nrow * 128 + ((gsel ^ (nrow & 7)) << 4));
                    #pragma unroll
                    for (int q = 0; q < 2; q++)
                        #pragma unroll
                        for (int mt = 0; mt < 2; mt++)
                            mma16816(o[mt][p * 2 + q], pa[mt], &bv[q*2]);
                }
            }
        }

        __syncthreads();
        if (kt + 2 < Tn / 64) issue_kv(kt + 2);
        CP_COMMIT();
    }

    // ---- normalize + transpose + store (row sums complete in ol) ----
    float i0[2], i1[2];
    #pragma unroll
    for (int mt = 0; mt < 2; mt++){ i0[mt] = 1.0f / ol[mt][0]; i1[mt] = 1.0f / ol[mt][2]; }

    __syncthreads();
    float* Cs = (float*)sm;   // [64 dh][128 q]
    const int r = lane >> 2, c2 = (lane & 3) * 2;
    #pragma unroll
    for (int mt = 0; mt < 2; mt++){
        const int qr = wid * 32 + mt * 16 + r;
        #pragma unroll
        for (int nt = 0; nt < 8; nt++){
            int col = nt * 8 + c2;
            Cs[col * 128 + qr]           = o[mt][nt][0] * i0[mt];
            Cs[(col + 1) * 128 + qr]     = o[mt][nt][1] * i0[mt];
            Cs[col * 128 + qr + 8]       = o[mt][nt][2] * i1[mt];
            Cs[(col + 1) * 128 + qr + 8] = o[mt][nt][3] * i1[mt];
        }
    }
    __syncthreads();

    const int dh = tid >> 1, q0 = (tid & 1) * 64;
    float* op = out + ((size_t)b * Dn + h * DHn + dh) * Tn + t0 + q0;
    #pragma unroll
    for (int i = 0; i < 64; i += 4)
        *(float4*)(op + i) = *(float4*)&Cs[dh * 128 + q0 + i];
}

extern "C" void kernel_launch(void* const* d_in, const int* in_sizes, int n_in,
                              void* d_out, int out_size){
    const float* x = (const float*)d_in[0];   // (B, D, T) fp32
    const float* w = (const float*)d_in[1];   // (3, H, D, Dh) fp32
    float* out = (float*)d_out;               // (B, D, T) fp32

    static bool configured = false;
    if (!configured){
        cudaFuncSetAttribute(qkv_mma_kernel,  cudaFuncAttributeMaxDynamicSharedMemorySize, 2 * QSTG);
        cudaFuncSetAttribute(attn_mma_kernel, cudaFuncAttributeMaxDynamicSharedMemorySize, AQR + 2 * AKVS);
        configured = true;
    }

    conv_kernel<<<1184, 256>>>((const float4*)x, (int)((size_t)Bn*Dn*Tn/4),
                               (const float4*)w, (int)((size_t)3*Hn*Dn*DHn/4));

    dim3 g1((Tn / 256) * Bn, 3 * Hn);     // (16, 48)
    qkv_mma_kernel<<<g1, 128, 2 * QSTG>>>();

    dim3 g2(Tn / 128, NBH);               // (16, 32)
    attn_mma_kernel<<<g2, 128, AQR + 2 * AKVS>>>(out);
}

// round 14
// speedup vs baseline: 1.0252x; 1.0252x over previous
#include <cuda_runtime.h>
#include <cuda_fp16.h>
#include <cstdint>

#define Bn 2
#define Dn 1024
#define Tn 2048
#define Hn 16
#define DHn 64
#define NBH (Bn*Hn)

// --------------- global scratch (plain fp16 everywhere) ---------------
__device__ __align__(16) __half gx [(size_t)Bn*Dn*Tn];          // x fp16
__device__ __align__(16) __half gw [(size_t)3*Hn*Dn*DHn];       // w fp16
__device__ __align__(16) __half g_q[(size_t)NBH*Tn*DHn];        // q [bh][t][dh], pre-scaled
__device__ __align__(16) __half g_k[(size_t)NBH*Tn*DHn];        // k [bh][t][dh]
__device__ __align__(16) __half g_v[(size_t)NBH*DHn*Tn];        // v [bh][dh][t]

// --------------- helpers ---------------
static __device__ __forceinline__ uint32_t smem_u32(const void* p){
    uint32_t a;
    asm("{ .reg .u64 t; cvta.to.shared.u64 t, %1; cvt.u32.u64 %0, t; }" : "=r"(a) : "l"(p));
    return a;
}
static __device__ __forceinline__ void cpa16(uint32_t dst, const void* src){
    asm volatile("cp.async.cg.shared.global [%0], [%1], 16;" :: "r"(dst), "l"(src));
}
#define CP_COMMIT() asm volatile("cp.async.commit_group;" ::: "memory")
#define CP_WAIT1()  asm volatile("cp.async.wait_group 1;" ::: "memory")

static __device__ __forceinline__ void ldsm4(uint32_t* r, uint32_t a){
    asm volatile("ldmatrix.sync.aligned.m8n8.x4.shared.b16 {%0,%1,%2,%3}, [%4];"
        : "=r"(r[0]),"=r"(r[1]),"=r"(r[2]),"=r"(r[3]) : "r"(a));
}
static __device__ __forceinline__ void ldsm4t(uint32_t* r, uint32_t a){
    asm volatile("ldmatrix.sync.aligned.m8n8.x4.trans.shared.b16 {%0,%1,%2,%3}, [%4];"
        : "=r"(r[0]),"=r"(r[1]),"=r"(r[2]),"=r"(r[3]) : "r"(a));
}
static __device__ __forceinline__ void mma16816(float* c, const uint32_t* a, const uint32_t* b){
    asm volatile("mma.sync.aligned.m16n8k16.row.col.f32.f16.f16.f32 "
        "{%0,%1,%2,%3}, {%4,%5,%6,%7}, {%8,%9}, {%0,%1,%2,%3};"
        : "+f"(c[0]), "+f"(c[1]), "+f"(c[2]), "+f"(c[3])
        : "r"(a[0]), "r"(a[1]), "r"(a[2]), "r"(a[3]), "r"(b[0]), "r"(b[1]));
}
static __device__ __forceinline__ uint32_t packh2(float e0, float e1){
    __half2 hv = __floats2half2_rn(e0, e1);
    return *(uint32_t*)&hv;
}
static __device__ __forceinline__ uint32_t ex2h2(uint32_t x){
    uint32_t r;
    asm("ex2.approx.f16x2 %0, %1;" : "=r"(r) : "r"(x));
    return r;
}

// --------------- prepass: fp32 -> fp16 (single fused kernel) ---------------
__global__ __launch_bounds__(256) void conv_kernel(const float4* __restrict__ xs, int nx4,
                                                   const float4* __restrict__ ws, int nw4){
    uint2* dx = (uint2*)gx;
    uint2* dw = (uint2*)gw;
    const int total = nx4 + nw4;
    for (int i = blockIdx.x*blockDim.x + threadIdx.x; i < total; i += gridDim.x*blockDim.x){
        float4 v = (i < nx4) ? xs[i] : ws[i - nx4];
        uint2 u;
        u.x = packh2(v.x, v.y);
        u.y = packh2(v.z, v.w);
        if (i < nx4) dx[i] = u; else dw[i - nx4] = u;
    }
}

// =====================================================================
// QKV GEMM (R12 version, proven): tile 128t x 64dh, 4 warps, warp =
// 32t x 64dh. grid=(32,48), block 128, 4 CTAs/SM (16 warps/SM).
// stage: A 16K ([d][t]) | B 8K ([d][dh]) = 24K x2.
// =====================================================================
#define QSTG 24576

__global__ __launch_bounds__(128, 4) void qkv_mma_kernel(){
    extern __shared__ char sm[];
    const uint32_t sb = smem_u32(sm);
    const int tid = threadIdx.x, lane = tid & 31, wid = tid >> 5;   // wid 0..3
    const int t0 = (blockIdx.x & 15) * 128;
    const int b  = blockIdx.x >> 4;
    const int nh = blockIdx.y;

    const __half* xp = gx + (size_t)b * Dn * Tn + t0;
    const __half* wp = gw + (size_t)nh * Dn * DHn;

    auto issue = [&](int s){
        const int d0 = s * 64;
        const uint32_t bi = sb + (s & 1) * QSTG;
        #pragma unroll
        for (int i = 0; i < 8; i++){           // A: 1024 16B-chunks
            int c = tid + i * 128;
            int d = c >> 4, g = c & 15;
            cpa16(bi + d * 256 + ((g ^ ((d & 7) << 1)) << 4),
                  xp + (size_t)(d0 + d) * Tn + g * 8);
        }
        #pragma unroll
        for (int i = 0; i < 4; i++){           // B: 512 chunks
            int c = tid + i * 128;
            int d = c >> 3, g = c & 7;
            cpa16(bi + 16384 + d * 128 + ((g ^ (d & 7)) << 4),
                  wp + (size_t)(d0 + d) * DHn + g * 8);
        }
    };

    float acc[2][8][4];
    #pragma unroll
    for (int i = 0; i < 2; i++)
        #pragma unroll
        for (int j = 0; j < 8; j++)
            #pragma unroll
            for (int k = 0; k < 4; k++) acc[i][j][k] = 0.f;

    issue(0); CP_COMMIT();
    issue(1); CP_COMMIT();

    #pragma unroll 1
    for (int s = 0; s < 16; s++){
        CP_WAIT1();
        __syncthreads();
        const uint32_t base = sb + (s & 1) * QSTG;

        #pragma unroll
        for (int k16 = 0; k16 < 4; k16++){
            const int k0 = k16 * 16;
            uint32_t ah[2][4];
            {
                int k = k0 + (lane & 7) + ((lane & 16) ? 8 : 0);
                #pragma unroll
                for (int mt = 0; mt < 2; mt++){
                    int gm = ((wid * 32 + mt * 16) >> 3) + ((lane & 8) ? 1 : 0);
                    ldsm4t(ah[mt], base + k * 256 + ((gm ^ ((k & 7) << 1)) << 4));
                }
            }
            {
                int k = k0 + (lane & 7) + ((lane & 8) ? 8 : 0);
                #pragma unroll
                for (int p = 0; p < 4; p++){
                    int gn = p * 2 + ((lane & 16) ? 1 : 0);
                    uint32_t bw[4];
                    ldsm4t(bw, base + 16384 + k * 128 + ((gn ^ (k & 7)) << 4));
                    #pragma unroll
                    for (int q = 0; q < 2; q++)
                        #pragma unroll
                        for (int mt = 0; mt < 2; mt++)
                            mma16816(acc[mt][p * 2 + q], ah[mt], &bw[q*2]);
                }
            }
        }
        __syncthreads();
        if (s + 2 < 16) issue(s + 2);
        CP_COMMIT();
    }
    __syncthreads();

    // epilogue
    const int n = nh >> 4, h = nh & 15, bh = b * Hn + h;
    const int r = lane >> 2, c2 = (lane & 3) * 2;
    if (n < 2){
        __half* dst = (n == 0 ? g_q : g_k) + (size_t)bh * Tn * DHn;
        const float sc = (n == 0) ? 0.125f * 1.44269504088896f : 1.0f;
        #pragma unroll
        for (int mt = 0; mt < 2; mt++)
            #pragma unroll
            for (int nt = 0; nt < 8; nt++){
                int t = t0 + wid * 32 + mt * 16 + r;
                int col = nt * 8 + c2;
                *(uint32_t*)(dst + (size_t)t * DHn + col) =
                    packh2(acc[mt][nt][0] * sc, acc[mt][nt][1] * sc);
                *(uint32_t*)(dst + (size_t)(t + 8) * DHn + col) =
                    packh2(acc[mt][nt][2] * sc, acc[mt][nt][3] * sc);
            }
    } else {
        float* Cs = (float*)sm;   // [64 dh][128 t]
        #pragma unroll
        for (int mt = 0; mt < 2; mt++)
            #pragma unroll
            for (int nt = 0; nt < 8; nt++){
                int t = wid * 32 + mt * 16 + r;
                int col = nt * 8 + c2;
                Cs[col * 128 + t]           = acc[mt][nt][0];
                Cs[(col + 1) * 128 + t]     = acc[mt][nt][1];
                Cs[col * 128 + t + 8]       = acc[mt][nt][2];
                Cs[(col + 1) * 128 + t + 8] = acc[mt][nt][3];
            }
        __syncthreads();
        const int dh = tid >> 1, q0 = (tid & 1) * 64;
        __half* ov = g_v + ((size_t)bh * DHn + dh) * Tn + t0 + q0;
        #pragma unroll
        for (int i = 0; i < 64; i += 2)
            *(uint32_t*)(ov + i) = packh2(Cs[dh * 128 + q0 + i], Cs[dh * 128 + q0 + i + 1]);
    }
}

// =====================================================================
// Attention: 128 q-rows per block, 4 warps (32 q-rows each), plain fp16.
// Keys processed in 16-key chunks (one k16 each): live S = s[2][2][4]
// (16 regs) -> total ~165 regs -> genuinely fits 3 CTAs/SM, no spills.
// ldsm/MMA counts per 64-key tile unchanged vs R12.
// smem: Q 16K | 2 x (K 8K + V 8K) = 48K.
// =====================================================================
#define AQR 16384
#define AKVS 16384

__global__ __launch_bounds__(128, 3) void attn_mma_kernel(float* __restrict__ out){
    extern __shared__ char sm[];
    const uint32_t sb = smem_u32(sm);
    const int tid = threadIdx.x, lane = tid & 31, wid = tid >> 5;   // wid 0..3
    const int t0 = blockIdx.x * 128;
    const int bh = blockIdx.y;
    const int b = bh >> 4, h = bh & 15;

    const __half* kb = g_k + (size_t)bh * Tn * DHn;
    const __half* vb = g_v + (size_t)bh * DHn * Tn;

    auto issue_kv = [&](int kt){
        const int tk = kt * 64;
        const uint32_t bi = sb + AQR + (kt & 1) * AKVS;
        #pragma unroll
        for (int i = 0; i < 4; i++){
            int c = tid + i * 128;
            int row = c >> 3, g = c & 7;
            cpa16(bi + row * 128 + ((g ^ (row & 7)) << 4),
                  kb + (size_t)(tk + row) * DHn + g * 8);
            cpa16(bi + 8192 + row * 128 + ((g ^ (row & 7)) << 4),
                  vb + (size_t)row * Tn + tk + g * 8);
        }
    };

    {
        const __half* qb = g_q + ((size_t)bh * Tn + t0) * DHn;
        #pragma unroll
        for (int i = 0; i < 8; i++){
            int c = tid + i * 128;
            int row = c >> 3, g = c & 7;
            cpa16(sb + row * 128 + ((g ^ (row & 7)) << 4),
                  qb + (size_t)row * DHn + g * 8);
        }
        issue_kv(0); CP_COMMIT();
        issue_kv(1); CP_COMMIT();
    }
    CP_WAIT1();
    __syncthreads();

    // Q fragments: warp owns rows wid*32 .. wid*32+31 (two m16 frags)
    uint32_t qf[2][4][4];
    #pragma unroll
    for (int mt = 0; mt < 2; mt++){
        const int m = wid * 32 + mt * 16 + (lane & 15);
        #pragma unroll
        for (int k16 = 0; k16 < 4; k16++){
            int g = k16 * 2 + ((lane & 16) ? 1 : 0);
            ldsm4(qf[mt][k16], sb + m * 128 + ((g ^ (m & 7)) << 4));
        }
    }

    float o[2][8][4];
    #pragma unroll
    for (int mt = 0; mt < 2; mt++)
        #pragma unroll
        for (int i = 0; i < 8; i++)
            #pragma unroll
            for (int j = 0; j < 4; j++) o[mt][i][j] = 0.f;
    float ol[2][4];   // row-sum accumulator via ones-MMA
    #pragma unroll
    for (int mt = 0; mt < 2; mt++)
        #pragma unroll
        for (int j = 0; j < 4; j++) ol[mt][j] = 0.f;
    const uint32_t ones2 = 0x3C003C00u;          // fp16 {1,1}
    const uint32_t bone[2] = {ones2, ones2};

    #pragma unroll 1
    for (int kt = 0; kt < Tn / 64; kt++){
        if (kt > 0){ CP_WAIT1(); __syncthreads(); }
        const uint32_t bi = sb + AQR + (kt & 1) * AKVS;
        const int nn = (lane & 7) + ((lane & 16) ? 8 : 0);

        // process the 64-key tile in four 16-key chunks (chunk = one k16 of PV)
        #pragma unroll
        for (int ck = 0; ck < 4; ck++){
            // ---- S (log2 domain) for 16 keys: rows ck*16 .. ck*16+15 ----
            float s[2][2][4];
            #pragma unroll
            for (int mt = 0; mt < 2; mt++)
                #pragma unroll
                for (int i = 0; i < 2; i++)
                    #pragma unroll
                    for (int j = 0; j < 4; j++) s[mt][i][j] = 0.f;

            {
                const int nrow = ck * 16 + nn;
                #pragma unroll
                for (int k16 = 0; k16 < 4; k16++){
                    const int gsel = k16 * 2 + ((lane & 8) ? 1 : 0);
                    uint32_t bk[4];
                    ldsm4(bk, bi + nrow * 128 + ((gsel ^ (nrow & 7)) << 4));
                    #pragma unroll
                    for (int q = 0; q < 2; q++)
                        #pragma unroll
                        for (int mt = 0; mt < 2; mt++)
                            mma16816(s[mt][q], qf[mt][k16], &bk[q*2]);
                }
            }

            // ---- P = exp2(S) fp16x2 (A-frag for PV k16=ck); rowsum MMA ----
            uint32_t pa[2][4];
            #pragma unroll
            for (int mt = 0; mt < 2; mt++){
                pa[mt][0] = ex2h2(packh2(s[mt][0][0], s[mt][0][1]));
                pa[mt][1] = ex2h2(packh2(s[mt][0][2], s[mt][0][3]));
                pa[mt][2] = ex2h2(packh2(s[mt][1][0], s[mt][1][1]));
                pa[mt][3] = ex2h2(packh2(s[mt][1][2], s[mt][1][3]));
                mma16816(ol[mt], pa[mt], bone);
            }

            // ---- O += P.V for this k16 ----
            {
                const int gsel = ck * 2 + ((lane & 8) ? 1 : 0);
                #pragma unroll
                for (int p = 0; p < 4; p++){
                    int nrow = p * 16 + nn;
                    uint32_t bv[4];
                    ldsm4(bv, bi + 8192 + nrow * 128 + ((gsel ^ (nrow & 7)) << 4));
                    #pragma unroll
                    for (int q = 0; q < 2; q++)
                        #pragma unroll
                        for (int mt = 0; mt < 2; mt++)
                            mma16816(o[mt][p * 2 + q], pa[mt], &bv[q*2]);
                }
            }
        }

        __syncthreads();
        if (kt + 2 < Tn / 64) issue_kv(kt + 2);
        CP_COMMIT();
    }

    // ---- normalize + transpose + store (row sums complete in ol) ----
    float i0[2], i1[2];
    #pragma unroll
    for (int mt = 0; mt < 2; mt++){ i0[mt] = 1.0f / ol[mt][0]; i1[mt] = 1.0f / ol[mt][2]; }

    __syncthreads();
    float* Cs = (float*)sm;   // [64 dh][128 q]
    const int r = lane >> 2, c2 = (lane & 3) * 2;
    #pragma unroll
    for (int mt = 0; mt < 2; mt++){
        const int qr = wid * 32 + mt * 16 + r;
        #pragma unroll
        for (int nt = 0; nt < 8; nt++){
            int col = nt * 8 + c2;
            Cs[col * 128 + qr]           = o[mt][nt][0] * i0[mt];
            Cs[(col + 1) * 128 + qr]     = o[mt][nt][1] * i0[mt];
            Cs[col * 128 + qr + 8]       = o[mt][nt][2] * i1[mt];
            Cs[(col + 1) * 128 + qr + 8] = o[mt][nt][3] * i1[mt];
        }
    }
    __syncthreads();

    const int dh = tid >> 1, q0 = (tid & 1) * 64;
    float* op = out + ((size_t)b * Dn + h * DHn + dh) * Tn + t0 + q0;
    #pragma unroll
    for (int i = 0; i < 64; i += 4)
        *(float4*)(op + i) = *(float4*)&Cs[dh * 128 + q0 + i];
}

extern "C" void kernel_launch(void* const* d_in, const int* in_sizes, int n_in,
                              void* d_out, int out_size){
    const float* x = (const float*)d_in[0];   // (B, D, T) fp32
    const float* w = (const float*)d_in[1];   // (3, H, D, Dh) fp32
    float* out = (float*)d_out;               // (B, D, T) fp32

    static bool configured = false;
    if (!configured){
        cudaFuncSetAttribute(qkv_mma_kernel,  cudaFuncAttributeMaxDynamicSharedMemorySize, 2 * QSTG);
        cudaFuncSetAttribute(attn_mma_kernel, cudaFuncAttributeMaxDynamicSharedMemorySize, AQR + 2 * AKVS);
        configured = true;
    }

    conv_kernel<<<1184, 256>>>((const float4*)x, (int)((size_t)Bn*Dn*Tn/4),
                               (const float4*)w, (int)((size_t)3*Hn*Dn*DHn/4));

    dim3 g1((Tn / 128) * Bn, 3 * Hn);     // (32, 48)
    qkv_mma_kernel<<<g1, 128, 2 * QSTG>>>();

    dim3 g2(Tn / 128, NBH);               // (16, 32)
    attn_mma_kernel<<<g2, 128, AQR + 2 * AKVS>>>(out);
}

// round 15
// speedup vs baseline: 1.0583x; 1.0323x over previous
#include <cuda_runtime.h>
#include <cuda_fp16.h>
#include <cstdint>

#define Bn 2
#define Dn 1024
#define Tn 2048
#define Hn 16
#define DHn 64
#define NBH (Bn*Hn)

// --------------- global scratch (plain fp16 everywhere) ---------------
__device__ __align__(16) __half gx [(size_t)Bn*Dn*Tn];          // x fp16
__device__ __align__(16) __half gw [(size_t)3*Hn*Dn*DHn];       // w fp16
__device__ __align__(16) __half g_q[(size_t)NBH*Tn*DHn];        // q [bh][t][dh], pre-scaled
__device__ __align__(16) __half g_k[(size_t)NBH*Tn*DHn];        // k [bh][t][dh]
__device__ __align__(16) __half g_v[(size_t)NBH*DHn*Tn];        // v [bh][dh][t]

// --------------- helpers ---------------
static __device__ __forceinline__ uint32_t smem_u32(const void* p){
    uint32_t a;
    asm("{ .reg .u64 t; cvta.to.shared.u64 t, %1; cvt.u32.u64 %0, t; }" : "=r"(a) : "l"(p));
    return a;
}
static __device__ __forceinline__ void cpa16(uint32_t dst, const void* src){
    asm volatile("cp.async.cg.shared.global [%0], [%1], 16;" :: "r"(dst), "l"(src));
}
#define CP_COMMIT() asm volatile("cp.async.commit_group;" ::: "memory")
#define CP_WAIT1()  asm volatile("cp.async.wait_group 1;" ::: "memory")

static __device__ __forceinline__ void ldsm4(uint32_t* r, uint32_t a){
    asm volatile("ldmatrix.sync.aligned.m8n8.x4.shared.b16 {%0,%1,%2,%3}, [%4];"
        : "=r"(r[0]),"=r"(r[1]),"=r"(r[2]),"=r"(r[3]) : "r"(a));
}
static __device__ __forceinline__ void ldsm4t(uint32_t* r, uint32_t a){
    asm volatile("ldmatrix.sync.aligned.m8n8.x4.trans.shared.b16 {%0,%1,%2,%3}, [%4];"
        : "=r"(r[0]),"=r"(r[1]),"=r"(r[2]),"=r"(r[3]) : "r"(a));
}
static __device__ __forceinline__ void mma16816(float* c, const uint32_t* a, const uint32_t* b){
    asm volatile("mma.sync.aligned.m16n8k16.row.col.f32.f16.f16.f32 "
        "{%0,%1,%2,%3}, {%4,%5,%6,%7}, {%8,%9}, {%0,%1,%2,%3};"
        : "+f"(c[0]), "+f"(c[1]), "+f"(c[2]), "+f"(c[3])
        : "r"(a[0]), "r"(a[1]), "r"(a[2]), "r"(a[3]), "r"(b[0]), "r"(b[1]));
}
static __device__ __forceinline__ uint32_t packh2(float e0, float e1){
    __half2 hv = __floats2half2_rn(e0, e1);
    return *(uint32_t*)&hv;
}
static __device__ __forceinline__ uint32_t ex2h2(uint32_t x){
    uint32_t r;
    asm("ex2.approx.f16x2 %0, %1;" : "=r"(r) : "r"(x));
    return r;
}

// --------------- prepass: fp32 -> fp16 (single fused kernel) ---------------
__global__ __launch_bounds__(256) void conv_kernel(const float4* __restrict__ xs, int nx4,
                                                   const float4* __restrict__ ws, int nw4){
    uint2* dx = (uint2*)gx;
    uint2* dw = (uint2*)gw;
    const int total = nx4 + nw4;
    for (int i = blockIdx.x*blockDim.x + threadIdx.x; i < total; i += gridDim.x*blockDim.x){
        float4 v = (i < nx4) ? xs[i] : ws[i - nx4];
        uint2 u;
        u.x = packh2(v.x, v.y);
        u.y = packh2(v.z, v.w);
        if (i < nx4) dx[i] = u; else dw[i - nx4] = u;
    }
}

// =====================================================================
// QKV GEMM: tile 128t x 64dh, 4 warps, warp = 32t x 64dh. grid=(32,48),
// block 128, 4 CTAs/SM (16 warps/SM). stage: A 16K | B 8K = 24K x2.
// A-tile swizzle FIXED to g^(d&15) (full 4-bit XOR): rows d and d^4 in
// the same ldsm phase previously collided on the 16B-bank map (X pairs
// differing by 8) -> every A-ldsm was a 2-way conflict. Now conflict-free.
// =====================================================================
#define QSTG 24576

__global__ __launch_bounds__(128, 4) void qkv_mma_kernel(){
    extern __shared__ char sm[];
    const uint32_t sb = smem_u32(sm);
    const int tid = threadIdx.x, lane = tid & 31, wid = tid >> 5;   // wid 0..3
    const int t0 = (blockIdx.x & 15) * 128;
    const int b  = blockIdx.x >> 4;
    const int nh = blockIdx.y;

    const __half* xp = gx + (size_t)b * Dn * Tn + t0;
    const __half* wp = gw + (size_t)nh * Dn * DHn;

    auto issue = [&](int s){
        const int d0 = s * 64;
        const uint32_t bi = sb + (s & 1) * QSTG;
        #pragma unroll
        for (int i = 0; i < 8; i++){           // A: 1024 16B-chunks
            int c = tid + i * 128;
            int d = c >> 4, g = c & 15;
            cpa16(bi + d * 256 + ((g ^ (d & 15)) << 4),
                  xp + (size_t)(d0 + d) * Tn + g * 8);
        }
        #pragma unroll
        for (int i = 0; i < 4; i++){           // B: 512 chunks
            int c = tid + i * 128;
            int d = c >> 3, g = c & 7;
            cpa16(bi + 16384 + d * 128 + ((g ^ (d & 7)) << 4),
                  wp + (size_t)(d0 + d) * DHn + g * 8);
        }
    };

    float acc[2][8][4];
    #pragma unroll
    for (int i = 0; i < 2; i++)
        #pragma unroll
        for (int j = 0; j < 8; j++)
            #pragma unroll
            for (int k = 0; k < 4; k++) acc[i][j][k] = 0.f;

    issue(0); CP_COMMIT();
    issue(1); CP_COMMIT();

    #pragma unroll 1
    for (int s = 0; s < 16; s++){
        CP_WAIT1();
        __syncthreads();
        const uint32_t base = sb + (s & 1) * QSTG;

        #pragma unroll
        for (int k16 = 0; k16 < 4; k16++){
            const int k0 = k16 * 16;
            uint32_t ah[2][4];
            {
                int k = k0 + (lane & 7) + ((lane & 16) ? 8 : 0);
                #pragma unroll
                for (int mt = 0; mt < 2; mt++){
                    int gm = ((wid * 32 + mt * 16) >> 3) + ((lane & 8) ? 1 : 0);
                    ldsm4t(ah[mt], base + k * 256 + ((gm ^ (k & 15)) << 4));
                }
            }
            {
                int k = k0 + (lane & 7) + ((lane & 8) ? 8 : 0);
                #pragma unroll
                for (int p = 0; p < 4; p++){
                    int gn = p * 2 + ((lane & 16) ? 1 : 0);
                    uint32_t bw[4];
                    ldsm4t(bw, base + 16384 + k * 128 + ((gn ^ (k & 7)) << 4));
                    #pragma unroll
                    for (int q = 0; q < 2; q++)
                        #pragma unroll
                        for (int mt = 0; mt < 2; mt++)
                            mma16816(acc[mt][p * 2 + q], ah[mt], &bw[q*2]);
                }
            }
        }
        __syncthreads();
        if (s + 2 < 16) issue(s + 2);
        CP_COMMIT();
    }
    __syncthreads();

    // epilogue
    const int n = nh >> 4, h = nh & 15, bh = b * Hn + h;
    const int r = lane >> 2, c2 = (lane & 3) * 2;
    if (n < 2){
        __half* dst = (n == 0 ? g_q : g_k) + (size_t)bh * Tn * DHn;
        const float sc = (n == 0) ? 0.125f * 1.44269504088896f : 1.0f;
        #pragma unroll
        for (int mt = 0; mt < 2; mt++)
            #pragma unroll
            for (int nt = 0; nt < 8; nt++){
                int t = t0 + wid * 32 + mt * 16 + r;
                int col = nt * 8 + c2;
                *(uint32_t*)(dst + (size_t)t * DHn + col) =
                    packh2(acc[mt][nt][0] * sc, acc[mt][nt][1] * sc);
                *(uint32_t*)(dst + (size_t)(t + 8) * DHn + col) =
                    packh2(acc[mt][nt][2] * sc, acc[mt][nt][3] * sc);
            }
    } else {
        float* Cs = (float*)sm;   // [64 dh][128 t]
        #pragma unroll
        for (int mt = 0; mt < 2; mt++)
            #pragma unroll
            for (int nt = 0; nt < 8; nt++){
                int t = wid * 32 + mt * 16 + r;
                int col = nt * 8 + c2;
                Cs[col * 128 + t]           = acc[mt][nt][0];
                Cs[(col + 1) * 128 + t]     = acc[mt][nt][1];
                Cs[col * 128 + t + 8]       = acc[mt][nt][2];
                Cs[(col + 1) * 128 + t + 8] = acc[mt][nt][3];
            }
        __syncthreads();
        const int dh = tid >> 1, q0 = (tid & 1) * 64;
        __half* ov = g_v + ((size_t)bh * DHn + dh) * Tn + t0 + q0;
        #pragma unroll
        for (int i = 0; i < 64; i += 2)
            *(uint32_t*)(ov + i) = packh2(Cs[dh * 128 + q0 + i], Cs[dh * 128 + q0 + i + 1]);
    }
}

// =====================================================================
// Attention (unchanged from R14): 128 q-rows per block, 4 warps, fp16.
// 16-key chunks; rowsum via ones-MMA. smem: Q 16K | 2 x 16K = 48K.
// =====================================================================
#define AQR 16384
#define AKVS 16384

__global__ __launch_bounds__(128, 3) void attn_mma_kernel(float* __restrict__ out){
    extern __shared__ char sm[];
    const uint32_t sb = smem_u32(sm);
    const int tid = threadIdx.x, lane = tid & 31, wid = tid >> 5;   // wid 0..3
    const int t0 = blockIdx.x * 128;
    const int bh = blockIdx.y;
    const int b = bh >> 4, h = bh & 15;

    const __half* kb = g_k + (size_t)bh * Tn * DHn;
    const __half* vb = g_v + (size_t)bh * DHn * Tn;

    auto issue_kv = [&](int kt){
        const int tk = kt * 64;
        const uint32_t bi = sb + AQR + (kt & 1) * AKVS;
        #pragma unroll
        for (int i = 0; i < 4; i++){
            int c = tid + i * 128;
            int row = c >> 3, g = c & 7;
            cpa16(bi + row * 128 + ((g ^ (row & 7)) << 4),
                  kb + (size_t)(tk + row) * DHn + g * 8);
            cpa16(bi + 8192 + row * 128 + ((g ^ (row & 7)) << 4),
                  vb + (size_t)row * Tn + tk + g * 8);
        }
    };

    {
        const __half* qb = g_q + ((size_t)bh * Tn + t0) * DHn;
        #pragma unroll
        for (int i = 0; i < 8; i++){
            int c = tid + i * 128;
            int row = c >> 3, g = c & 7;
            cpa16(sb + row * 128 + ((g ^ (row & 7)) << 4),
                  qb + (size_t)row * DHn + g * 8);
        }
        issue_kv(0); CP_COMMIT();
        issue_kv(1); CP_COMMIT();
    }
    CP_WAIT1();
    __syncthreads();

    // Q fragments: warp owns rows wid*32 .. wid*32+31 (two m16 frags)
    uint32_t qf[2][4][4];
    #pragma unroll
    for (int mt = 0; mt < 2; mt++){
        const int m = wid * 32 + mt * 16 + (lane & 15);
        #pragma unroll
        for (int k16 = 0; k16 < 4; k16++){
            int g = k16 * 2 + ((lane & 16) ? 1 : 0);
            ldsm4(qf[mt][k16], sb + m * 128 + ((g ^ (m & 7)) << 4));
        }
    }

    float o[2][8][4];
    #pragma unroll
    for (int mt = 0; mt < 2; mt++)
        #pragma unroll
        for (int i = 0; i < 8; i++)
            #pragma unroll
            for (int j = 0; j < 4; j++) o[mt][i][j] = 0.f;
    float ol[2][4];   // row-sum accumulator via ones-MMA
    #pragma unroll
    for (int mt = 0; mt < 2; mt++)
        #pragma unroll
        for (int j = 0; j < 4; j++) ol[mt][j] = 0.f;
    const uint32_t ones2 = 0x3C003C00u;          // fp16 {1,1}
    const uint32_t bone[2] = {ones2, ones2};

    #pragma unroll 1
    for (int kt = 0; kt < Tn / 64; kt++){
        if (kt > 0){ CP_WAIT1(); __syncthreads(); }
        const uint32_t bi = sb + AQR + (kt & 1) * AKVS;
        const int nn = (lane & 7) + ((lane & 16) ? 8 : 0);

        #pragma unroll
        for (int ck = 0; ck < 4; ck++){
            float s[2][2][4];
            #pragma unroll
            for (int mt = 0; mt < 2; mt++)
                #pragma unroll
                for (int i = 0; i < 2; i++)
                    #pragma unroll
                    for (int j = 0; j < 4; j++) s[mt][i][j] = 0.f;

            {
                const int nrow = ck * 16 + nn;
                #pragma unroll
                for (int k16 = 0; k16 < 4; k16++){
                    const int gsel = k16 * 2 + ((lane & 8) ? 1 : 0);
                    uint32_t bk[4];
                    ldsm4(bk, bi + nrow * 128 + ((gsel ^ (nrow & 7)) << 4));
                    #pragma unroll
                    for (int q = 0; q < 2; q++)
                        #pragma unroll
                        for (int mt = 0; mt < 2; mt++)
                            mma16816(s[mt][q], qf[mt][k16], &bk[q*2]);
                }
            }

            uint32_t pa[2][4];
            #pragma unroll
            for (int mt = 0; mt < 2; mt++){
                pa[mt][0] = ex2h2(packh2(s[mt][0][0], s[mt][0][1]));
                pa[mt][1] = ex2h2(packh2(s[mt][0][2], s[mt][0][3]));
                pa[mt][2] = ex2h2(packh2(s[mt][1][0], s[mt][1][1]));
                pa[mt][3] = ex2h2(packh2(s[mt][1][2], s[mt][1][3]));
                mma16816(ol[mt], pa[mt], bone);
            }

            {
                const int gsel = ck * 2 + ((lane & 8) ? 1 : 0);
                #pragma unroll
                for (int p = 0; p < 4; p++){
                    int nrow = p * 16 + nn;
                    uint32_t bv[4];
                    ldsm4(bv, bi + 8192 + nrow * 128 + ((gsel ^ (nrow & 7)) << 4));
                    #pragma unroll
                    for (int q = 0; q < 2; q++)
                        #pragma unroll
                        for (int mt = 0; mt < 2; mt++)
                            mma16816(o[mt][p * 2 + q], pa[mt], &bv[q*2]);
                }
            }
        }

        __syncthreads();
        if (kt + 2 < Tn / 64) issue_kv(kt + 2);
        CP_COMMIT();
    }

    // ---- normalize + transpose + store (row sums complete in ol) ----
    float i0[2], i1[2];
    #pragma unroll
    for (int mt = 0; mt < 2; mt++){ i0[mt] = 1.0f / ol[mt][0]; i1[mt] = 1.0f / ol[mt][2]; }

    __syncthreads();
    float* Cs = (float*)sm;   // [64 dh][128 q]
    const int r = lane >> 2, c2 = (lane & 3) * 2;
    #pragma unroll
    for (int mt = 0; mt < 2; mt++){
        const int qr = wid * 32 + mt * 16 + r;
        #pragma unroll
        for (int nt = 0; nt < 8; nt++){
            int col = nt * 8 + c2;
            Cs[col * 128 + qr]           = o[mt][nt][0] * i0[mt];
            Cs[(col + 1) * 128 + qr]     = o[mt][nt][1] * i0[mt];
            Cs[col * 128 + qr + 8]       = o[mt][nt][2] * i1[mt];
            Cs[(col + 1) * 128 + qr + 8] = o[mt][nt][3] * i1[mt];
        }
    }
    __syncthreads();

    const int dh = tid >> 1, q0 = (tid & 1) * 64;
    float* op = out + ((size_t)b * Dn + h * DHn + dh) * Tn + t0 + q0;
    #pragma unroll
    for (int i = 0; i < 64; i += 4)
        *(float4*)(op + i) = *(float4*)&Cs[dh * 128 + q0 + i];
}

extern "C" void kernel_launch(void* const* d_in, const int* in_sizes, int n_in,
                              void* d_out, int out_size){
    const float* x = (const float*)d_in[0];   // (B, D, T) fp32
    const float* w = (const float*)d_in[1];   // (3, H, D, Dh) fp32
    float* out = (float*)d_out;               // (B, D, T) fp32

    static bool configured = false;
    if (!configured){
        cudaFuncSetAttribute(qkv_mma_kernel,  cudaFuncAttributeMaxDynamicSharedMemorySize, 2 * QSTG);
        cudaFuncSetAttribute(attn_mma_kernel, cudaFuncAttributeMaxDynamicSharedMemorySize, AQR + 2 * AKVS);
        configured = true;
    }

    conv_kernel<<<1184, 256>>>((const float4*)x, (int)((size_t)Bn*Dn*Tn/4),
                               (const float4*)w, (int)((size_t)3*Hn*Dn*DHn/4));

    dim3 g1((Tn / 128) * Bn, 3 * Hn);     // (32, 48)
    qkv_mma_kernel<<<g1, 128, 2 * QSTG>>>();

    dim3 g2(Tn / 128, NBH);               // (16, 32)
    attn_mma_kernel<<<g2, 128, AQR + 2 * AKVS>>>(out);
}